// round 5
// baseline (speedup 1.0000x reference)
#include <cuda_runtime.h>

#define NPTS 6912
#define CF 16
#define BB 2
#define TILE 128
#define NT (NPTS / TILE)     /* 54 */
#define PREPB (NPTS / 256)   /* 27 */
#define EPSF 1e-8f
/* exp(-sq/0.1) = 2^(NEG_SCALE * sq) */
#define NEG_SCALE (-14.426950408889634f)
#define POS2SCALE (28.853900817779268f)

typedef unsigned long long u64;

/* ------------------------- device scratch ------------------------------- */
__device__ float  g_f1d[BB][CF][2 * NPTS];  /* f1 normalized, duplicated (v,v) */
__device__ float  g_f2n[BB][CF][NPTS];      /* f2 normalized */
__device__ float  g_x1d[BB][4][2 * NPTS];   /* rows 0-2: POS2SCALE*x1 dup; row 3: as dup */
__device__ float  g_xt [BB][3][NPTS];       /* xyz2 transformed */
__device__ float  g_xn [BB][3][NPTS];       /* xyz2 noisy */
__device__ float  g_bts[BB][NPTS];          /* NEG_SCALE*||xt||^2 */
__device__ float  g_bns[BB][NPTS];          /* NEG_SCALE*||xn||^2 */
__device__ float  g_part[BB][PREPB][3];     /* per-block: fns, sum m1, sum m2 */
__device__ double g_S[BB];

/* ------------------------- packed f32x2 helpers ------------------------- */
__device__ __forceinline__ float2 unpk(u64 v) {
    float2 r; asm("mov.b64 {%0, %1}, %2;" : "=f"(r.x), "=f"(r.y) : "l"(v)); return r;
}
__device__ __forceinline__ void fma2(u64 &d, u64 a, u64 b) {
    asm("fma.rn.f32x2 %0, %1, %2, %0;" : "+l"(d) : "l"(a), "l"(b));
}
__device__ __forceinline__ u64 add2(u64 a, u64 b) {
    u64 r; asm("add.rn.f32x2 %0, %1, %2;" : "=l"(r) : "l"(a), "l"(b)); return r;
}
__device__ __forceinline__ float fexp2(float x) {
    float r; asm("ex2.approx.f32 %0, %1;" : "=f"(r) : "f"(x)); return r;
}

/* ------------------------- prep: per-point quantities ------------------- */
__global__ void prep_kernel(const float* __restrict__ f1, const float* __restrict__ f2,
                            const float* __restrict__ dp1, const float* __restrict__ dp2,
                            const float* __restrict__ pose, const float* __restrict__ yz1) {
    const int b = blockIdx.y;
    const int i = blockIdx.x * blockDim.x + threadIdx.x;
    float fns, m1c, m2c;
    {
        float d1 = dp1[b * NPTS + i], d2 = dp2[b * NPTS + i];
        float m1 = (d1 > 0.f) ? 1.f : 0.f;
        float m2 = (d2 > 0.f) ? 1.f : 0.f;
        float v1[CF], v2[CF];
        float s1 = 0.f, s2 = 0.f;
#pragma unroll
        for (int c = 0; c < CF; c++) {
            v1[c] = f1[((size_t)b * CF + c) * NPTS + i];
            v2[c] = f2[((size_t)b * CF + c) * NPTS + i];
            s1 = fmaf(v1[c], v1[c], s1);
            s2 = fmaf(v2[c], v2[c], s2);
        }
        float n1 = sqrtf(s1), n2 = sqrtf(s2);
        float iv1 = m1 / (n1 + EPSF), iv2 = m2 / (n2 + EPSF);
#pragma unroll
        for (int c = 0; c < CF; c++) {
            float a = v1[c] * iv1;
            g_f1d[b][c][2 * i]     = a;
            g_f1d[b][c][2 * i + 1] = a;
            g_f2n[b][c][i] = v2[c] * iv2;
        }
        float y0 = yz1[i], y1 = yz1[NPTS + i], y2 = yz1[2 * NPTS + i];
        float ax = y0 * d1, ay = y1 * d1, az = y2 * d1;
        float as = NEG_SCALE * (ax * ax + ay * ay + az * az);
        g_x1d[b][0][2 * i] = g_x1d[b][0][2 * i + 1] = POS2SCALE * ax;
        g_x1d[b][1][2 * i] = g_x1d[b][1][2 * i + 1] = POS2SCALE * ay;
        g_x1d[b][2][2 * i] = g_x1d[b][2][2 * i + 1] = POS2SCALE * az;
        g_x1d[b][3][2 * i] = g_x1d[b][3][2 * i + 1] = as;
        float bx = y0 * d2, by = y1 * d2, bz = y2 * d2;
        g_xn[b][0][i] = bx; g_xn[b][1][i] = by; g_xn[b][2][i] = bz;
        g_bns[b][i] = NEG_SCALE * (bx * bx + by * by + bz * bz);
        const float* P = pose + b * 16;
        float tx = P[0] * bx + P[1] * by + P[2]  * bz + P[3];
        float ty = P[4] * bx + P[5] * by + P[6]  * bz + P[7];
        float tz = P[8] * bx + P[9] * by + P[10] * bz + P[11];
        g_xt[b][0][i] = tx; g_xt[b][1][i] = ty; g_xt[b][2][i] = tz;
        g_bts[b][i] = NEG_SCALE * (tx * tx + ty * ty + tz * tz);
        fns = n1 * m1 + n2 * m2; m1c = m1; m2c = m2;
    }
#pragma unroll
    for (int o = 16; o; o >>= 1) {
        fns += __shfl_down_sync(0xffffffffu, fns, o);
        m1c += __shfl_down_sync(0xffffffffu, m1c, o);
        m2c += __shfl_down_sync(0xffffffffu, m2c, o);
    }
    __shared__ float rf[8], r1[8], r2[8];
    int w = threadIdx.x >> 5, l = threadIdx.x & 31;
    if (l == 0) { rf[w] = fns; r1[w] = m1c; r2[w] = m2c; }
    __syncthreads();
    if (threadIdx.x == 0) {
        float a = 0.f, c1 = 0.f, c2 = 0.f;
#pragma unroll
        for (int k = 0; k < 8; k++) { a += rf[k]; c1 += r1[k]; c2 += r2[k]; }
        g_part[b][blockIdx.x][0] = a;
        g_part[b][blockIdx.x][1] = c1;
        g_part[b][blockIdx.x][2] = c2;
        if (blockIdx.x == 0) g_S[b] = 0.0;   /* zero before pair_kernel runs */
    }
}

/* ------------------------- main: 128x128 pair tiles, occ=2 -------------- */
__global__ __launch_bounds__(512, 2) void pair_kernel() {
    const int b  = blockIdx.z;
    const int i0 = blockIdx.y * TILE;
    const int j0 = blockIdx.x * TILE;

    __shared__ __align__(16) float sA2[CF][2 * TILE];   /* dup f1: 16KB */
    __shared__ __align__(16) float sB [CF][TILE];       /* f2: 8KB */
    __shared__ __align__(16) float sX1d[4][2 * TILE];   /* dup i-geom: 4KB */
    __shared__ __align__(16) float sJT[3][TILE];
    __shared__ __align__(16) float sJN[3][TILE];
    __shared__ __align__(16) float sbt[TILE], sbn[TILE];

    const int tid = threadIdx.x;

    /* cooperative tile loads, all float4 */
    {
#pragma unroll
        for (int k = 0; k < 2; k++) {                 /* sA2: 1024 float4 */
            int idx = tid + k * 512;
            int c = idx >> 6, q = idx & 63;
            ((float4*)sA2)[idx] = *(const float4*)&g_f1d[b][c][2 * i0 + q * 4];
        }
        {                                             /* sB: 512 float4 */
            int c = tid >> 5, q = tid & 31;
            ((float4*)sB)[tid] = *(const float4*)&g_f2n[b][c][j0 + q * 4];
        }
        if (tid < 256) {                              /* sX1d: 256 float4 */
            int r = tid >> 6, q = tid & 63;
            ((float4*)sX1d)[tid] = *(const float4*)&g_x1d[b][r][2 * i0 + q * 4];
        } else {                                      /* j-side geometry: 256 float4 */
            int t = tid - 256;
            if (t < 96) {
                int r = t >> 5, q = t & 31;
                ((float4*)sJT)[t] = *(const float4*)&g_xt[b][r][j0 + q * 4];
            } else if (t < 192) {
                int t2 = t - 96, r = t2 >> 5, q = t2 & 31;
                ((float4*)sJN)[t2] = *(const float4*)&g_xn[b][r][j0 + q * 4];
            } else if (t < 224) {
                ((float4*)sbt)[t - 192] = *(const float4*)&g_bts[b][j0 + (t - 192) * 4];
            } else {
                ((float4*)sbn)[t - 224] = *(const float4*)&g_bns[b][j0 + (t - 224) * 4];
            }
        }
    }
    __syncthreads();

    const int ty = tid >> 5;   /* warp id 0..15: 8 i rows (warp-uniform a-side) */
    const int tx = tid & 31;   /* lane: 4 j cols, split in two jp passes */
    const int iL = ty * 8;

    float part = 0.f;

    /* two passes over the thread's j-pair halves: keeps acc + j-hoist small
       so two blocks fit per SM and fma/MUFU phases overlap across blocks */
#pragma unroll
    for (int jp = 0; jp < 2; jp++) {
        const int jL = tx * 4 + jp * 2;

        /* ---- gramian for this j-pair: 8i x 2j ---- */
        u64 acc[8];
#pragma unroll
        for (int ii = 0; ii < 8; ii++) acc[ii] = 0ull;

#pragma unroll
        for (int c = 0; c < CF; c++) {
            const float* arow = &sA2[c][ty * 16];
            u64 ad[8];
#pragma unroll
            for (int p = 0; p < 4; p++) {             /* broadcast LDS.128 */
                ulonglong2 v = *(const ulonglong2*)&arow[p * 4];
                ad[2 * p] = v.x; ad[2 * p + 1] = v.y;
            }
            u64 bv = *(const u64*)&sB[c][jL];         /* native j-pair */
#pragma unroll
            for (int ii = 0; ii < 8; ii++)
                fma2(acc[ii], ad[ii], bv);
        }

        /* ---- RBF for this j-pair ---- */
        u64 T0 = *(const u64*)&sJT[0][jL];
        u64 T1 = *(const u64*)&sJT[1][jL];
        u64 T2 = *(const u64*)&sJT[2][jL];
        u64 N0 = *(const u64*)&sJN[0][jL];
        u64 N1 = *(const u64*)&sJN[1][jL];
        u64 N2 = *(const u64*)&sJN[2][jL];
        u64 BT = *(const u64*)&sbt[jL];
        u64 BN = *(const u64*)&sbn[jL];

#pragma unroll
        for (int ii = 0; ii < 8; ii++) {
            const int i2 = (iL + ii) * 2;
            u64 xd0 = *(const u64*)&sX1d[0][i2];   /* broadcast LDS.64, pre-dup'd */
            u64 xd1 = *(const u64*)&sX1d[1][i2];
            u64 xd2 = *(const u64*)&sX1d[2][i2];
            u64 asd = *(const u64*)&sX1d[3][i2];

            u64 st = add2(asd, BT);
            fma2(st, xd0, T0); fma2(st, xd1, T1); fma2(st, xd2, T2);
            u64 sn = add2(asd, BN);
            fma2(sn, xd0, N0); fma2(sn, xd1, N1); fma2(sn, xd2, N2);
            float2 stf = unpk(st), snf = unpk(sn), g = unpk(acc[ii]);
            part = fmaf(fexp2(stf.x) - fexp2(snf.x), g.x, part);
            part = fmaf(fexp2(stf.y) - fexp2(snf.y), g.y, part);
        }
    }

    /* ---- block reduce -> one double atomic ---- */
#pragma unroll
    for (int o = 16; o; o >>= 1) part += __shfl_down_sync(0xffffffffu, part, o);
    __shared__ float warpsum[16];
    if ((tid & 31) == 0) warpsum[tid >> 5] = part;
    __syncthreads();
    if (tid == 0) {
        float s = 0.f;
#pragma unroll
        for (int w = 0; w < 16; w++) s += warpsum[w];
        atomicAdd(&g_S[b], (double)s);
    }
}

/* ------------------------- finalize ------------------------------------ */
__global__ void fin_kernel(float* out) {
    double tot = 0.0;
    float fns = 0.f;
#pragma unroll
    for (int b = 0; b < BB; b++) {
        float s1 = 0.f, s2 = 0.f;
        for (int k = 0; k < PREPB; k++) {
            fns += g_part[b][k][0];
            s1  += g_part[b][k][1];
            s2  += g_part[b][k][2];
        }
        tot += g_S[b] / ((double)s1 * (double)s2);
    }
    float fl = (float)(-tot);
    out[0] = fl;
    out[1] = fl;
    out[2] = fns * 100.f;
}

/* ------------------------- launch --------------------------------------- */
extern "C" void kernel_launch(void* const* d_in, const int* in_sizes, int n_in,
                              void* d_out, int out_size) {
    const float* f1   = (const float*)d_in[0];
    const float* f2   = (const float*)d_in[1];
    const float* dp1  = (const float*)d_in[2];
    const float* dp2  = (const float*)d_in[3];
    const float* pose = (const float*)d_in[4];
    const float* yz1  = (const float*)d_in[7];
    float* out = (float*)d_out;

    prep_kernel<<<dim3(PREPB, BB), 256>>>(f1, f2, dp1, dp2, pose, yz1);
    pair_kernel<<<dim3(NT, NT, BB), 512>>>();
    fin_kernel<<<1, 1>>>(out);
}

// round 6
// speedup vs baseline: 7.0963x; 7.0963x over previous
#include <cuda_runtime.h>

#define NPTS 6912
#define CF 16
#define BB 2
#define TILE 128
#define NT (NPTS / TILE)     /* 54 */
#define PREPB (NPTS / 256)   /* 27 */
#define EPSF 1e-8f
/* exp(-sq/0.1) = 2^(NEG_SCALE * sq) */
#define NEG_SCALE (-14.426950408889634f)
#define POS2SCALE (28.853900817779268f)

typedef unsigned long long u64;

/* ------------------------- device scratch ------------------------------- */
__device__ float  g_f1d[BB][CF][2 * NPTS];  /* f1 normalized, duplicated (v,v) */
__device__ float  g_f2n[BB][CF][NPTS];      /* f2 normalized */
__device__ float  g_x1d[BB][4][2 * NPTS];   /* rows 0-2: POS2SCALE*x1 dup; row 3: as dup */
__device__ float  g_xt [BB][3][NPTS];       /* xyz2 transformed */
__device__ float  g_xn [BB][3][NPTS];       /* xyz2 noisy */
__device__ float  g_bts[BB][NPTS];          /* NEG_SCALE*||xt||^2 */
__device__ float  g_bns[BB][NPTS];          /* NEG_SCALE*||xn||^2 */
__device__ float  g_part[BB][PREPB][3];     /* per-block: fns, sum m1, sum m2 */
__device__ double g_S[BB];

/* ------------------------- packed f32x2 helpers ------------------------- */
__device__ __forceinline__ u64 pack2(float lo, float hi) {
    u64 r; asm("mov.b64 %0, {%1, %2};" : "=l"(r) : "f"(lo), "f"(hi)); return r;
}
__device__ __forceinline__ float2 unpk(u64 v) {
    float2 r; asm("mov.b64 {%0, %1}, %2;" : "=f"(r.x), "=f"(r.y) : "l"(v)); return r;
}
__device__ __forceinline__ void fma2(u64 &d, u64 a, u64 b) {
    asm("fma.rn.f32x2 %0, %1, %2, %0;" : "+l"(d) : "l"(a), "l"(b));
}
__device__ __forceinline__ u64 add2(u64 a, u64 b) {
    u64 r; asm("add.rn.f32x2 %0, %1, %2;" : "=l"(r) : "l"(a), "l"(b)); return r;
}
__device__ __forceinline__ float fexp2(float x) {
    float r; asm("ex2.approx.f32 %0, %1;" : "=f"(r) : "f"(x)); return r;
}

/* ------------------------- prep: per-point quantities ------------------- */
__global__ void prep_kernel(const float* __restrict__ f1, const float* __restrict__ f2,
                            const float* __restrict__ dp1, const float* __restrict__ dp2,
                            const float* __restrict__ pose, const float* __restrict__ yz1) {
    const int b = blockIdx.y;
    const int i = blockIdx.x * blockDim.x + threadIdx.x;
    float fns, m1c, m2c;
    {
        float d1 = dp1[b * NPTS + i], d2 = dp2[b * NPTS + i];
        float m1 = (d1 > 0.f) ? 1.f : 0.f;
        float m2 = (d2 > 0.f) ? 1.f : 0.f;
        float v1[CF], v2[CF];
        float s1 = 0.f, s2 = 0.f;
#pragma unroll
        for (int c = 0; c < CF; c++) {
            v1[c] = f1[((size_t)b * CF + c) * NPTS + i];
            v2[c] = f2[((size_t)b * CF + c) * NPTS + i];
            s1 = fmaf(v1[c], v1[c], s1);
            s2 = fmaf(v2[c], v2[c], s2);
        }
        float n1 = sqrtf(s1), n2 = sqrtf(s2);
        float iv1 = m1 / (n1 + EPSF), iv2 = m2 / (n2 + EPSF);
#pragma unroll
        for (int c = 0; c < CF; c++) {
            float a = v1[c] * iv1;
            g_f1d[b][c][2 * i]     = a;
            g_f1d[b][c][2 * i + 1] = a;
            g_f2n[b][c][i] = v2[c] * iv2;
        }
        float y0 = yz1[i], y1 = yz1[NPTS + i], y2 = yz1[2 * NPTS + i];
        float ax = y0 * d1, ay = y1 * d1, az = y2 * d1;
        float as = NEG_SCALE * (ax * ax + ay * ay + az * az);
        g_x1d[b][0][2 * i] = g_x1d[b][0][2 * i + 1] = POS2SCALE * ax;
        g_x1d[b][1][2 * i] = g_x1d[b][1][2 * i + 1] = POS2SCALE * ay;
        g_x1d[b][2][2 * i] = g_x1d[b][2][2 * i + 1] = POS2SCALE * az;
        g_x1d[b][3][2 * i] = g_x1d[b][3][2 * i + 1] = as;
        float bx = y0 * d2, by = y1 * d2, bz = y2 * d2;
        g_xn[b][0][i] = bx; g_xn[b][1][i] = by; g_xn[b][2][i] = bz;
        g_bns[b][i] = NEG_SCALE * (bx * bx + by * by + bz * bz);
        const float* P = pose + b * 16;
        float tx = P[0] * bx + P[1] * by + P[2]  * bz + P[3];
        float ty = P[4] * bx + P[5] * by + P[6]  * bz + P[7];
        float tz = P[8] * bx + P[9] * by + P[10] * bz + P[11];
        g_xt[b][0][i] = tx; g_xt[b][1][i] = ty; g_xt[b][2][i] = tz;
        g_bts[b][i] = NEG_SCALE * (tx * tx + ty * ty + tz * tz);
        fns = n1 * m1 + n2 * m2; m1c = m1; m2c = m2;
    }
#pragma unroll
    for (int o = 16; o; o >>= 1) {
        fns += __shfl_down_sync(0xffffffffu, fns, o);
        m1c += __shfl_down_sync(0xffffffffu, m1c, o);
        m2c += __shfl_down_sync(0xffffffffu, m2c, o);
    }
    __shared__ float rf[8], r1[8], r2[8];
    int w = threadIdx.x >> 5, l = threadIdx.x & 31;
    if (l == 0) { rf[w] = fns; r1[w] = m1c; r2[w] = m2c; }
    __syncthreads();
    if (threadIdx.x == 0) {
        float a = 0.f, c1 = 0.f, c2 = 0.f;
#pragma unroll
        for (int k = 0; k < 8; k++) { a += rf[k]; c1 += r1[k]; c2 += r2[k]; }
        g_part[b][blockIdx.x][0] = a;
        g_part[b][blockIdx.x][1] = c1;
        g_part[b][blockIdx.x][2] = c2;
        if (blockIdx.x == 0) g_S[b] = 0.0;   /* zero before pair_kernel runs */
    }
}

/* ------------------------- main: 128x128 pair tiles --------------------- */
/* occ=1 by design; MUFU work is issued FIRST so it retires under the gram
   FMA stream (in-order issue, scoreboard joins only at the final combine). */
__global__ __launch_bounds__(512, 1) void pair_kernel() {
    const int b  = blockIdx.z;
    const int i0 = blockIdx.y * TILE;
    const int j0 = blockIdx.x * TILE;

    __shared__ __align__(16) float sA2[CF][2 * TILE];   /* dup f1: 16KB */
    __shared__ __align__(16) float sB [CF][TILE];       /* f2: 8KB */
    __shared__ __align__(16) float sX1d[4][2 * TILE];   /* dup i-geom: 4KB */
    __shared__ __align__(16) float sJT[3][TILE];
    __shared__ __align__(16) float sJN[3][TILE];
    __shared__ __align__(16) float sbt[TILE], sbn[TILE];

    const int tid = threadIdx.x;

    /* cooperative tile loads, all float4 */
    {
#pragma unroll
        for (int k = 0; k < 2; k++) {                 /* sA2: 1024 float4 */
            int idx = tid + k * 512;
            int c = idx >> 6, q = idx & 63;
            ((float4*)sA2)[idx] = *(const float4*)&g_f1d[b][c][2 * i0 + q * 4];
        }
        {                                             /* sB: 512 float4 */
            int c = tid >> 5, q = tid & 31;
            ((float4*)sB)[tid] = *(const float4*)&g_f2n[b][c][j0 + q * 4];
        }
        if (tid < 256) {                              /* sX1d: 256 float4 */
            int r = tid >> 6, q = tid & 63;
            ((float4*)sX1d)[tid] = *(const float4*)&g_x1d[b][r][2 * i0 + q * 4];
        } else {                                      /* j-side geometry: 256 float4 */
            int t = tid - 256;
            if (t < 96) {
                int r = t >> 5, q = t & 31;
                ((float4*)sJT)[t] = *(const float4*)&g_xt[b][r][j0 + q * 4];
            } else if (t < 192) {
                int t2 = t - 96, r = t2 >> 5, q = t2 & 31;
                ((float4*)sJN)[t2] = *(const float4*)&g_xn[b][r][j0 + q * 4];
            } else if (t < 224) {
                ((float4*)sbt)[t - 192] = *(const float4*)&g_bts[b][j0 + (t - 192) * 4];
            } else {
                ((float4*)sbn)[t - 224] = *(const float4*)&g_bns[b][j0 + (t - 224) * 4];
            }
        }
    }
    __syncthreads();

    const int ty = tid >> 5;   /* warp id 0..15: 8 i rows (warp-uniform a-side) */
    const int tx = tid & 31;   /* lane: 4 j cols */
    const int iL = ty * 8;
    const int jL = tx * 4;

    /* ---- Phase 1: RBF weights FIRST (MUFU issues early, retires under
            the gram FMA stream). w[ii][jp] = packed (e_t - e_n) pair. ---- */
    u64 w[8][2];
    {
        u64 T0 = *(const u64*)&sJT[0][jL], T0b = *(const u64*)&sJT[0][jL + 2];
        u64 T1 = *(const u64*)&sJT[1][jL], T1b = *(const u64*)&sJT[1][jL + 2];
        u64 T2 = *(const u64*)&sJT[2][jL], T2b = *(const u64*)&sJT[2][jL + 2];
        u64 N0 = *(const u64*)&sJN[0][jL], N0b = *(const u64*)&sJN[0][jL + 2];
        u64 N1 = *(const u64*)&sJN[1][jL], N1b = *(const u64*)&sJN[1][jL + 2];
        u64 N2 = *(const u64*)&sJN[2][jL], N2b = *(const u64*)&sJN[2][jL + 2];
        u64 BT = *(const u64*)&sbt[jL],    BTb = *(const u64*)&sbt[jL + 2];
        u64 BN = *(const u64*)&sbn[jL],    BNb = *(const u64*)&sbn[jL + 2];

#pragma unroll
        for (int ii = 0; ii < 8; ii++) {
            const int i2 = (iL + ii) * 2;
            u64 xd0 = *(const u64*)&sX1d[0][i2];   /* broadcast LDS.64, pre-dup'd */
            u64 xd1 = *(const u64*)&sX1d[1][i2];
            u64 xd2 = *(const u64*)&sX1d[2][i2];
            u64 asd = *(const u64*)&sX1d[3][i2];

            u64 st0 = add2(asd, BT);
            fma2(st0, xd0, T0);  fma2(st0, xd1, T1);  fma2(st0, xd2, T2);
            u64 sn0 = add2(asd, BN);
            fma2(sn0, xd0, N0);  fma2(sn0, xd1, N1);  fma2(sn0, xd2, N2);
            u64 st1 = add2(asd, BTb);
            fma2(st1, xd0, T0b); fma2(st1, xd1, T1b); fma2(st1, xd2, T2b);
            u64 sn1 = add2(asd, BNb);
            fma2(sn1, xd0, N0b); fma2(sn1, xd1, N1b); fma2(sn1, xd2, N2b);

            float2 s0 = unpk(st0), n0 = unpk(sn0);
            float2 s1 = unpk(st1), n1 = unpk(sn1);
            w[ii][0] = pack2(fexp2(s0.x) - fexp2(n0.x), fexp2(s0.y) - fexp2(n0.y));
            w[ii][1] = pack2(fexp2(s1.x) - fexp2(n1.x), fexp2(s1.y) - fexp2(n1.y));
        }
    }

    /* ---- Phase 2: gramian 8i x 4j, packed over j-pairs (as R1) ---- */
    u64 acc[8][2];
#pragma unroll
    for (int ii = 0; ii < 8; ii++) { acc[ii][0] = 0ull; acc[ii][1] = 0ull; }

#pragma unroll
    for (int c = 0; c < CF; c++) {
        const float* arow = &sA2[c][ty * 16];
        u64 ad[8];
#pragma unroll
        for (int p = 0; p < 4; p++) {                 /* broadcast LDS.128 */
            ulonglong2 v = *(const ulonglong2*)&arow[p * 4];
            ad[2 * p] = v.x; ad[2 * p + 1] = v.y;
        }
        ulonglong2 bv = *(const ulonglong2*)&sB[c][jL];
#pragma unroll
        for (int ii = 0; ii < 8; ii++) {
            fma2(acc[ii][0], ad[ii], bv.x);
            fma2(acc[ii][1], ad[ii], bv.y);
        }
    }

    /* ---- Phase 3: combine w . g (packed) ---- */
    u64 p2a = 0ull, p2b = 0ull;
#pragma unroll
    for (int ii = 0; ii < 8; ii++) {
        fma2(p2a, w[ii][0], acc[ii][0]);
        fma2(p2b, w[ii][1], acc[ii][1]);
    }
    float2 pa = unpk(p2a), pb = unpk(p2b);
    float part = (pa.x + pa.y) + (pb.x + pb.y);

    /* ---- block reduce -> one double atomic ---- */
#pragma unroll
    for (int o = 16; o; o >>= 1) part += __shfl_down_sync(0xffffffffu, part, o);
    __shared__ float warpsum[16];
    if ((tid & 31) == 0) warpsum[tid >> 5] = part;
    __syncthreads();
    if (tid == 0) {
        float s = 0.f;
#pragma unroll
        for (int w2 = 0; w2 < 16; w2++) s += warpsum[w2];
        atomicAdd(&g_S[b], (double)s);
    }
}

/* ------------------------- finalize ------------------------------------ */
__global__ void fin_kernel(float* out) {
    double tot = 0.0;
    float fns = 0.f;
#pragma unroll
    for (int b = 0; b < BB; b++) {
        float s1 = 0.f, s2 = 0.f;
        for (int k = 0; k < PREPB; k++) {
            fns += g_part[b][k][0];
            s1  += g_part[b][k][1];
            s2  += g_part[b][k][2];
        }
        tot += g_S[b] / ((double)s1 * (double)s2);
    }
    float fl = (float)(-tot);
    out[0] = fl;
    out[1] = fl;
    out[2] = fns * 100.f;
}

/* ------------------------- launch --------------------------------------- */
extern "C" void kernel_launch(void* const* d_in, const int* in_sizes, int n_in,
                              void* d_out, int out_size) {
    const float* f1   = (const float*)d_in[0];
    const float* f2   = (const float*)d_in[1];
    const float* dp1  = (const float*)d_in[2];
    const float* dp2  = (const float*)d_in[3];
    const float* pose = (const float*)d_in[4];
    const float* yz1  = (const float*)d_in[7];
    float* out = (float*)d_out;

    prep_kernel<<<dim3(PREPB, BB), 256>>>(f1, f2, dp1, dp2, pose, yz1);
    pair_kernel<<<dim3(NT, NT, BB), 512>>>();
    fin_kernel<<<1, 1>>>(out);
}

// round 11
// speedup vs baseline: 9.5391x; 1.3442x over previous
#include <cuda_runtime.h>
#include <cuda_bf16.h>
#include <cstdint>

#define NPTS 6912
#define CF 16
#define BB 2
#define TILE 128
#define NT (NPTS / TILE)     /* 54 */
#define PREPB (NPTS / 256)   /* 27 */
#define EPSF 1e-8f
/* exp(-sq/0.1) = 2^(NEG_SCALE * sq) */
#define NEG_SCALE (-14.426950408889634f)
#define POS2SCALE (28.853900817779268f)
#define ROWP 24   /* bf16 elems per tile row (16 used + 8 pad) -> 48B stride */

typedef unsigned long long u64;

/* ------------------------- device scratch ------------------------------- */
/* bf16 hi/lo split tiles: [split][row][ROWP]; rows 48B apart, 16B aligned */
__device__ __nv_bfloat16 g_fA[BB][NT][2][TILE][ROWP];
__device__ __nv_bfloat16 g_fB[BB][NT][2][TILE][ROWP];
__device__ float  g_x1i[BB][NPTS][8];   /* {Px,Px,Py,Py,Pz,Pz,as,as} */
__device__ float  g_xt [BB][3][NPTS];
__device__ float  g_xn [BB][3][NPTS];
__device__ float  g_bts[BB][NPTS];
__device__ float  g_bns[BB][NPTS];
__device__ float  g_part[BB][PREPB][3];
__device__ double g_S[BB];

/* ------------------------- helpers -------------------------------------- */
__device__ __forceinline__ float2 unpk(u64 v) {
    float2 r; asm("mov.b64 {%0, %1}, %2;" : "=f"(r.x), "=f"(r.y) : "l"(v)); return r;
}
__device__ __forceinline__ void fma2(u64 &d, u64 a, u64 b) {
    asm("fma.rn.f32x2 %0, %1, %2, %0;" : "+l"(d) : "l"(a), "l"(b));
}
__device__ __forceinline__ u64 add2(u64 a, u64 b) {
    u64 r; asm("add.rn.f32x2 %0, %1, %2;" : "=l"(r) : "l"(a), "l"(b)); return r;
}
__device__ __forceinline__ float fexp2(float x) {
    float r; asm("ex2.approx.f32 %0, %1;" : "=f"(r) : "f"(x)); return r;
}
__device__ __forceinline__ uint32_t s2u(const void* p) {
    uint32_t a;
    asm("{ .reg .u64 t; cvta.to.shared.u64 t, %1; cvt.u32.u64 %0, t; }" : "=r"(a) : "l"(p));
    return a;
}
__device__ __forceinline__ void ldsm4(uint32_t r[4], uint32_t addr) {
    asm volatile("ldmatrix.sync.aligned.m8n8.x4.shared.b16 {%0,%1,%2,%3}, [%4];"
                 : "=r"(r[0]), "=r"(r[1]), "=r"(r[2]), "=r"(r[3]) : "r"(addr));
}
__device__ __forceinline__ void mma_bf16(float d[4], const uint32_t a[4],
                                         uint32_t b0, uint32_t b1) {
    asm volatile("mma.sync.aligned.m16n8k16.row.col.f32.bf16.bf16.f32 "
                 "{%0,%1,%2,%3}, {%4,%5,%6,%7}, {%8,%9}, {%0,%1,%2,%3};"
                 : "+f"(d[0]), "+f"(d[1]), "+f"(d[2]), "+f"(d[3])
                 : "r"(a[0]), "r"(a[1]), "r"(a[2]), "r"(a[3]), "r"(b0), "r"(b1));
}

/* ------------------------- prep ----------------------------------------- */
__global__ void prep_kernel(const float* __restrict__ f1, const float* __restrict__ f2,
                            const float* __restrict__ dp1, const float* __restrict__ dp2,
                            const float* __restrict__ pose, const float* __restrict__ yz1) {
    const int b = blockIdx.y;
    const int i = blockIdx.x * blockDim.x + threadIdx.x;
    const int tile = i >> 7, row = i & 127;
    float fns, m1c, m2c;
    {
        float d1 = dp1[b * NPTS + i], d2 = dp2[b * NPTS + i];
        float m1 = (d1 > 0.f) ? 1.f : 0.f;
        float m2 = (d2 > 0.f) ? 1.f : 0.f;
        float v1[CF], v2[CF];
        float s1 = 0.f, s2 = 0.f;
#pragma unroll
        for (int c = 0; c < CF; c++) {
            v1[c] = f1[((size_t)b * CF + c) * NPTS + i];
            v2[c] = f2[((size_t)b * CF + c) * NPTS + i];
            s1 = fmaf(v1[c], v1[c], s1);
            s2 = fmaf(v2[c], v2[c], s2);
        }
        float n1 = sqrtf(s1), n2 = sqrtf(s2);
        float iv1 = m1 / (n1 + EPSF), iv2 = m2 / (n2 + EPSF);

        union { uint4 q[2]; __nv_bfloat162 h[8]; } AH, AL, BH, BL;
#pragma unroll
        for (int t = 0; t < 8; t++) {
            float a0 = v1[2 * t] * iv1,     a1 = v1[2 * t + 1] * iv1;
            __nv_bfloat16 h0 = __float2bfloat16(a0), h1 = __float2bfloat16(a1);
            AH.h[t].x = h0; AH.h[t].y = h1;
            AL.h[t].x = __float2bfloat16(a0 - __bfloat162float(h0));
            AL.h[t].y = __float2bfloat16(a1 - __bfloat162float(h1));
            float b0 = v2[2 * t] * iv2,     b1 = v2[2 * t + 1] * iv2;
            __nv_bfloat16 g0 = __float2bfloat16(b0), g1 = __float2bfloat16(b1);
            BH.h[t].x = g0; BH.h[t].y = g1;
            BL.h[t].x = __float2bfloat16(b0 - __bfloat162float(g0));
            BL.h[t].y = __float2bfloat16(b1 - __bfloat162float(g1));
        }
        *(uint4*)&g_fA[b][tile][0][row][0] = AH.q[0];
        *(uint4*)&g_fA[b][tile][0][row][8] = AH.q[1];
        *(uint4*)&g_fA[b][tile][1][row][0] = AL.q[0];
        *(uint4*)&g_fA[b][tile][1][row][8] = AL.q[1];
        *(uint4*)&g_fB[b][tile][0][row][0] = BH.q[0];
        *(uint4*)&g_fB[b][tile][0][row][8] = BH.q[1];
        *(uint4*)&g_fB[b][tile][1][row][0] = BL.q[0];
        *(uint4*)&g_fB[b][tile][1][row][8] = BL.q[1];

        float y0 = yz1[i], y1 = yz1[NPTS + i], y2 = yz1[2 * NPTS + i];
        float ax = y0 * d1, ay = y1 * d1, az = y2 * d1;
        float as = NEG_SCALE * (ax * ax + ay * ay + az * az);
        float4 ia = make_float4(POS2SCALE * ax, POS2SCALE * ax, POS2SCALE * ay, POS2SCALE * ay);
        float4 ib = make_float4(POS2SCALE * az, POS2SCALE * az, as, as);
        *(float4*)&g_x1i[b][i][0] = ia;
        *(float4*)&g_x1i[b][i][4] = ib;

        float bx = y0 * d2, by = y1 * d2, bz = y2 * d2;
        g_xn[b][0][i] = bx; g_xn[b][1][i] = by; g_xn[b][2][i] = bz;
        g_bns[b][i] = NEG_SCALE * (bx * bx + by * by + bz * bz);
        const float* P = pose + b * 16;
        float tx = P[0] * bx + P[1] * by + P[2]  * bz + P[3];
        float ty = P[4] * bx + P[5] * by + P[6]  * bz + P[7];
        float tz = P[8] * bx + P[9] * by + P[10] * bz + P[11];
        g_xt[b][0][i] = tx; g_xt[b][1][i] = ty; g_xt[b][2][i] = tz;
        g_bts[b][i] = NEG_SCALE * (tx * tx + ty * ty + tz * tz);
        fns = n1 * m1 + n2 * m2; m1c = m1; m2c = m2;
    }
#pragma unroll
    for (int o = 16; o; o >>= 1) {
        fns += __shfl_down_sync(0xffffffffu, fns, o);
        m1c += __shfl_down_sync(0xffffffffu, m1c, o);
        m2c += __shfl_down_sync(0xffffffffu, m2c, o);
    }
    __shared__ float rf[8], r1[8], r2[8];
    int w = threadIdx.x >> 5, l = threadIdx.x & 31;
    if (l == 0) { rf[w] = fns; r1[w] = m1c; r2[w] = m2c; }
    __syncthreads();
    if (threadIdx.x == 0) {
        float a = 0.f, c1 = 0.f, c2 = 0.f;
#pragma unroll
        for (int k = 0; k < 8; k++) { a += rf[k]; c1 += r1[k]; c2 += r2[k]; }
        g_part[b][blockIdx.x][0] = a;
        g_part[b][blockIdx.x][1] = c1;
        g_part[b][blockIdx.x][2] = c2;
        if (blockIdx.x == 0) g_S[b] = 0.0;
    }
}

/* ------------------------- pair: HMMA gramian + MUFU RBF ----------------- */
struct SmemT {
    __nv_bfloat16 A[2][TILE][ROWP];     /* 12KB */
    __nv_bfloat16 B[2][TILE][ROWP];     /* 12KB */
    __align__(16) float X1i[TILE][8];   /* 4KB */
    __align__(16) float JT[3][TILE];
    __align__(16) float JN[3][TILE];
    __align__(16) float bt[TILE], bn[TILE];
    __align__(16) float warpsum[16];
};

__global__ void __launch_bounds__(512, 1) pair_kernel() {
    __shared__ SmemT sm;
    const int b  = blockIdx.z;
    const int i0 = blockIdx.y * TILE;
    const int j0 = blockIdx.x * TILE;
    const int tid = threadIdx.x;
    const int w = tid >> 5, lane = tid & 31;
    const int wy = w >> 2, wx = w & 3;       /* warp (i,j) slab: 32x32 */

    /* tile fills (dense float4 copies; split layout prepacked in prep) */
    {
        const float4* sa = (const float4*)g_fA[b][blockIdx.y];
        const float4* sb = (const float4*)g_fB[b][blockIdx.x];
        ((float4*)sm.A)[tid] = sa[tid];
        ((float4*)sm.B)[tid] = sb[tid];
        if (tid < 256) {
            ((float4*)sm.A)[512 + tid] = sa[512 + tid];
            ((float4*)sm.B)[512 + tid] = sb[512 + tid];
            ((float4*)sm.X1i)[tid] = ((const float4*)&g_x1i[b][i0][0])[tid];
        } else {
            int t = tid - 256;
            if (t < 96) {
                int r = t >> 5, q = t & 31;
                ((float4*)sm.JT)[t] = *(const float4*)&g_xt[b][r][j0 + q * 4];
            } else if (t < 192) {
                int t2 = t - 96, r = t2 >> 5, q = t2 & 31;
                ((float4*)sm.JN)[t2] = *(const float4*)&g_xn[b][r][j0 + q * 4];
            } else if (t < 224) {
                ((float4*)sm.bt)[t - 192] = *(const float4*)&g_bts[b][j0 + (t - 192) * 4];
            } else {
                ((float4*)sm.bn)[t - 224] = *(const float4*)&g_bns[b][j0 + (t - 224) * 4];
            }
        }
    }
    __syncthreads();

    /* ---- gramian on tensor pipe: bf16 3-term split, 24 HMMA/warp ---- */
    uint32_t af[2][2][4];                     /* [mi][split][4] */
#pragma unroll
    for (int mi = 0; mi < 2; mi++)
#pragma unroll
        for (int s = 0; s < 2; s++) {
            int row = wy * 32 + mi * 16 + (lane & 15);
            int kh  = (lane >> 4) * 8;
            ldsm4(af[mi][s], s2u(&sm.A[s][row][kh]));
        }
    uint32_t bfr[2][2][4];                    /* [np][split][4]: tiles 2np,2np+1 */
#pragma unroll
    for (int np = 0; np < 2; np++)
#pragma unroll
        for (int s = 0; s < 2; s++) {
            int row = wx * 32 + np * 16 + ((lane >> 4) & 1) * 8 + (lane & 7);
            int kh  = ((lane >> 3) & 1) * 8;
            ldsm4(bfr[np][s], s2u(&sm.B[s][row][kh]));
        }

    float acc[2][4][4];
#pragma unroll
    for (int mi = 0; mi < 2; mi++)
#pragma unroll
        for (int ni = 0; ni < 4; ni++) {
#pragma unroll
            for (int k = 0; k < 4; k++) acc[mi][ni][k] = 0.f;
            const int np = ni >> 1, o = (ni & 1) * 2;
            mma_bf16(acc[mi][ni], af[mi][0], bfr[np][0][o], bfr[np][0][o + 1]); /* ah*bh */
            mma_bf16(acc[mi][ni], af[mi][0], bfr[np][1][o], bfr[np][1][o + 1]); /* ah*bl */
            mma_bf16(acc[mi][ni], af[mi][1], bfr[np][0][o], bfr[np][0][o + 1]); /* al*bh */
        }

    /* ---- RBF weights + combine ---- */
    const int r = lane >> 2;
    ulonglong2 I1[4], I2[4];                  /* (Px,Px),(Py,Py) / (Pz,Pz),(as,as) */
#pragma unroll
    for (int q = 0; q < 4; q++) {
        int irow = wy * 32 + q * 8 + r;       /* q = mi*2+half */
        I1[q] = *(const ulonglong2*)&sm.X1i[irow][0];
        I2[q] = *(const ulonglong2*)&sm.X1i[irow][4];
    }

    float part = 0.f;
#pragma unroll
    for (int ni = 0; ni < 4; ni++) {
        const int jc = wx * 32 + ni * 8 + 2 * (lane & 3);
        u64 T0 = *(const u64*)&sm.JT[0][jc];
        u64 T1 = *(const u64*)&sm.JT[1][jc];
        u64 T2 = *(const u64*)&sm.JT[2][jc];
        u64 N0 = *(const u64*)&sm.JN[0][jc];
        u64 N1 = *(const u64*)&sm.JN[1][jc];
        u64 N2 = *(const u64*)&sm.JN[2][jc];
        u64 BT = *(const u64*)&sm.bt[jc];
        u64 BN = *(const u64*)&sm.bn[jc];
#pragma unroll
        for (int q = 0; q < 4; q++) {
            const int mi = q >> 1, half = q & 1;
            u64 st = add2(I2[q].y, BT);
            fma2(st, I1[q].x, T0); fma2(st, I1[q].y, T1); fma2(st, I2[q].x, T2);
            u64 sn = add2(I2[q].y, BN);
            fma2(sn, I1[q].x, N0); fma2(sn, I1[q].y, N1); fma2(sn, I2[q].x, N2);
            float2 s = unpk(st), n = unpk(sn);
            float w0 = fexp2(s.x) - fexp2(n.x);
            float w1 = fexp2(s.y) - fexp2(n.y);
            part = fmaf(w0, acc[mi][ni][half * 2],     part);
            part = fmaf(w1, acc[mi][ni][half * 2 + 1], part);
        }
    }

    /* ---- block reduce -> one double atomic ---- */
#pragma unroll
    for (int o = 16; o; o >>= 1) part += __shfl_down_sync(0xffffffffu, part, o);
    if (lane == 0) sm.warpsum[w] = part;
    __syncthreads();
    if (tid == 0) {
        float s = 0.f;
#pragma unroll
        for (int k = 0; k < 16; k++) s += sm.warpsum[k];
        atomicAdd(&g_S[b], (double)s);
    }
}

/* ------------------------- finalize ------------------------------------- */
__global__ void fin_kernel(float* out) {
    double tot = 0.0;
    float fns = 0.f;
#pragma unroll
    for (int b = 0; b < BB; b++) {
        float s1 = 0.f, s2 = 0.f;
        for (int k = 0; k < PREPB; k++) {
            fns += g_part[b][k][0];
            s1  += g_part[b][k][1];
            s2  += g_part[b][k][2];
        }
        tot += g_S[b] / ((double)s1 * (double)s2);
    }
    float fl = (float)(-tot);
    out[0] = fl;
    out[1] = fl;
    out[2] = fns * 100.f;
}

/* ------------------------- launch ---------------------------------------- */
extern "C" void kernel_launch(void* const* d_in, const int* in_sizes, int n_in,
                              void* d_out, int out_size) {
    const float* f1   = (const float*)d_in[0];
    const float* f2   = (const float*)d_in[1];
    const float* dp1  = (const float*)d_in[2];
    const float* dp2  = (const float*)d_in[3];
    const float* pose = (const float*)d_in[4];
    const float* yz1  = (const float*)d_in[7];
    float* out = (float*)d_out;

    prep_kernel<<<dim3(PREPB, BB), 256>>>(f1, f2, dp1, dp2, pose, yz1);
    pair_kernel<<<dim3(NT, NT, BB), 512>>>();
    fin_kernel<<<1, 1>>>(out);
}

// round 13
// speedup vs baseline: 11.6190x; 1.2180x over previous
#include <cuda_runtime.h>
#include <cuda_bf16.h>
#include <cstdint>

#define NPTS 6912
#define CF 16
#define BB 2
#define TILE 128
#define NT (NPTS / TILE)     /* 54 */
#define JCHUNK 6
#define NJB (NT / JCHUNK)    /* 9 */
#define PREPB (NPTS / 256)   /* 27 */
#define EPSF 1e-8f
#define NEG_SCALE (-14.426950408889634f)
#define POS2SCALE (28.853900817779268f)
#define ROWP 24              /* bf16/row: 16 used + 8 pad -> 48B stride */

typedef unsigned long long u64;

/* ------------------------- packed per-tile records ----------------------- */
struct APack {               /* 16384 B */
    __nv_bfloat16 A[2][TILE][ROWP];     /* hi/lo split, 12KB */
    float X1i[TILE][8];                 /* {Px,Px,Py,Py,Pz,Pz,as,as} 4KB */
};
struct JPack {               /* 16384 B */
    __nv_bfloat16 B[2][TILE][ROWP];     /* 12KB */
    float JT[3][TILE];
    float JN[3][TILE];
    float bt[TILE], bn[TILE];
};

__device__ APack g_ap[BB][NT];
__device__ JPack g_jp[BB][NT];
__device__ float  g_part[BB][PREPB][3];
__device__ double g_S[BB];

/* ------------------------- helpers -------------------------------------- */
__device__ __forceinline__ float2 unpk(u64 v) {
    float2 r; asm("mov.b64 {%0, %1}, %2;" : "=f"(r.x), "=f"(r.y) : "l"(v)); return r;
}
__device__ __forceinline__ void fma2(u64 &d, u64 a, u64 b) {
    asm("fma.rn.f32x2 %0, %1, %2, %0;" : "+l"(d) : "l"(a), "l"(b));
}
__device__ __forceinline__ u64 add2(u64 a, u64 b) {
    u64 r; asm("add.rn.f32x2 %0, %1, %2;" : "=l"(r) : "l"(a), "l"(b)); return r;
}
__device__ __forceinline__ float fexp2(float x) {
    float r; asm("ex2.approx.f32 %0, %1;" : "=f"(r) : "f"(x)); return r;
}
__device__ __forceinline__ uint32_t s2u(const void* p) {
    uint32_t a;
    asm("{ .reg .u64 t; cvta.to.shared.u64 t, %1; cvt.u32.u64 %0, t; }" : "=r"(a) : "l"(p));
    return a;
}
__device__ __forceinline__ void ldsm4(uint32_t r[4], uint32_t addr) {
    asm volatile("ldmatrix.sync.aligned.m8n8.x4.shared.b16 {%0,%1,%2,%3}, [%4];"
                 : "=r"(r[0]), "=r"(r[1]), "=r"(r[2]), "=r"(r[3]) : "r"(addr));
}
__device__ __forceinline__ void mma_bf16(float d[4], const uint32_t a[4],
                                         uint32_t b0, uint32_t b1) {
    asm volatile("mma.sync.aligned.m16n8k16.row.col.f32.bf16.bf16.f32 "
                 "{%0,%1,%2,%3}, {%4,%5,%6,%7}, {%8,%9}, {%0,%1,%2,%3};"
                 : "+f"(d[0]), "+f"(d[1]), "+f"(d[2]), "+f"(d[3])
                 : "r"(a[0]), "r"(a[1]), "r"(a[2]), "r"(a[3]), "r"(b0), "r"(b1));
}
__device__ __forceinline__ void cpa16(uint32_t dst, const void* src) {
    asm volatile("cp.async.cg.shared.global [%0], [%1], 16;" :: "r"(dst), "l"(src));
}
#define CPA_COMMIT() asm volatile("cp.async.commit_group;" ::: "memory")
#define CPA_WAIT0()  asm volatile("cp.async.wait_group 0;" ::: "memory")

/* ------------------------- prep ----------------------------------------- */
__global__ void prep_kernel(const float* __restrict__ f1, const float* __restrict__ f2,
                            const float* __restrict__ dp1, const float* __restrict__ dp2,
                            const float* __restrict__ pose, const float* __restrict__ yz1) {
    const int b = blockIdx.y;
    const int i = blockIdx.x * blockDim.x + threadIdx.x;
    const int tile = i >> 7, row = i & 127;
    float fns, m1c, m2c;
    {
        float d1 = dp1[b * NPTS + i], d2 = dp2[b * NPTS + i];
        float m1 = (d1 > 0.f) ? 1.f : 0.f;
        float m2 = (d2 > 0.f) ? 1.f : 0.f;
        float v1[CF], v2[CF];
        float s1 = 0.f, s2 = 0.f;
#pragma unroll
        for (int c = 0; c < CF; c++) {
            v1[c] = f1[((size_t)b * CF + c) * NPTS + i];
            v2[c] = f2[((size_t)b * CF + c) * NPTS + i];
            s1 = fmaf(v1[c], v1[c], s1);
            s2 = fmaf(v2[c], v2[c], s2);
        }
        float n1 = sqrtf(s1), n2 = sqrtf(s2);
        float iv1 = m1 / (n1 + EPSF), iv2 = m2 / (n2 + EPSF);

        union { uint4 q[2]; __nv_bfloat162 h[8]; } AH, AL, BH, BL;
#pragma unroll
        for (int t = 0; t < 8; t++) {
            float a0 = v1[2 * t] * iv1,     a1 = v1[2 * t + 1] * iv1;
            __nv_bfloat16 h0 = __float2bfloat16(a0), h1 = __float2bfloat16(a1);
            AH.h[t].x = h0; AH.h[t].y = h1;
            AL.h[t].x = __float2bfloat16(a0 - __bfloat162float(h0));
            AL.h[t].y = __float2bfloat16(a1 - __bfloat162float(h1));
            float b0 = v2[2 * t] * iv2,     b1 = v2[2 * t + 1] * iv2;
            __nv_bfloat16 g0 = __float2bfloat16(b0), g1 = __float2bfloat16(b1);
            BH.h[t].x = g0; BH.h[t].y = g1;
            BL.h[t].x = __float2bfloat16(b0 - __bfloat162float(g0));
            BL.h[t].y = __float2bfloat16(b1 - __bfloat162float(g1));
        }
        APack& ap = g_ap[b][tile];
        JPack& jp = g_jp[b][tile];
        *(uint4*)&ap.A[0][row][0] = AH.q[0];
        *(uint4*)&ap.A[0][row][8] = AH.q[1];
        *(uint4*)&ap.A[1][row][0] = AL.q[0];
        *(uint4*)&ap.A[1][row][8] = AL.q[1];
        *(uint4*)&jp.B[0][row][0] = BH.q[0];
        *(uint4*)&jp.B[0][row][8] = BH.q[1];
        *(uint4*)&jp.B[1][row][0] = BL.q[0];
        *(uint4*)&jp.B[1][row][8] = BL.q[1];

        float y0 = yz1[i], y1 = yz1[NPTS + i], y2 = yz1[2 * NPTS + i];
        float ax = y0 * d1, ay = y1 * d1, az = y2 * d1;
        float as = NEG_SCALE * (ax * ax + ay * ay + az * az);
        *(float4*)&ap.X1i[row][0] = make_float4(POS2SCALE * ax, POS2SCALE * ax,
                                                POS2SCALE * ay, POS2SCALE * ay);
        *(float4*)&ap.X1i[row][4] = make_float4(POS2SCALE * az, POS2SCALE * az, as, as);

        float bx = y0 * d2, by = y1 * d2, bz = y2 * d2;
        jp.JN[0][row] = bx; jp.JN[1][row] = by; jp.JN[2][row] = bz;
        jp.bn[row] = NEG_SCALE * (bx * bx + by * by + bz * bz);
        const float* P = pose + b * 16;
        float tx = P[0] * bx + P[1] * by + P[2]  * bz + P[3];
        float ty = P[4] * bx + P[5] * by + P[6]  * bz + P[7];
        float tz = P[8] * bx + P[9] * by + P[10] * bz + P[11];
        jp.JT[0][row] = tx; jp.JT[1][row] = ty; jp.JT[2][row] = tz;
        jp.bt[row] = NEG_SCALE * (tx * tx + ty * ty + tz * tz);
        fns = n1 * m1 + n2 * m2; m1c = m1; m2c = m2;
    }
#pragma unroll
    for (int o = 16; o; o >>= 1) {
        fns += __shfl_down_sync(0xffffffffu, fns, o);
        m1c += __shfl_down_sync(0xffffffffu, m1c, o);
        m2c += __shfl_down_sync(0xffffffffu, m2c, o);
    }
    __shared__ float rf[8], r1[8], r2[8];
    int w = threadIdx.x >> 5, l = threadIdx.x & 31;
    if (l == 0) { rf[w] = fns; r1[w] = m1c; r2[w] = m2c; }
    __syncthreads();
    if (threadIdx.x == 0) {
        float a = 0.f, c1 = 0.f, c2 = 0.f;
#pragma unroll
        for (int k = 0; k < 8; k++) { a += rf[k]; c1 += r1[k]; c2 += r2[k]; }
        g_part[b][blockIdx.x][0] = a;
        g_part[b][blockIdx.x][1] = c1;
        g_part[b][blockIdx.x][2] = c2;
        if (blockIdx.x == 0) g_S[b] = 0.0;
    }
}

/* ------------------------- pair: persistent i-strip, 6 j-tiles ----------- */
struct SmemT {
    APack ap;            /* 16KB */
    JPack jb[2];         /* 32KB double buffer */
    float warpsum[16];
};

__global__ void __launch_bounds__(512, 1) pair_kernel() {
    __shared__ SmemT sm;
    const int b     = blockIdx.z;
    const int ti    = blockIdx.y;
    const int jbase = blockIdx.x * JCHUNK;
    const int tid = threadIdx.x;
    const int w = tid >> 5, lane = tid & 31;
    const int wy = w >> 2, wx = w & 3;       /* warp (i,j) slab: 32x32 */

    /* prologue: async-fill A-pack + first J-pack */
    {
        const float4* ga = (const float4*)&g_ap[b][ti];
        float4* sa = (float4*)&sm.ap;
        cpa16(s2u(sa + tid), ga + tid);
        cpa16(s2u(sa + tid + 512), ga + tid + 512);
        const float4* gj = (const float4*)&g_jp[b][jbase];
        float4* sj = (float4*)&sm.jb[0];
        cpa16(s2u(sj + tid), gj + tid);
        cpa16(s2u(sj + tid + 512), gj + tid + 512);
        CPA_COMMIT();
        CPA_WAIT0();
    }
    __syncthreads();

    /* A fragments: pinned in registers for the whole strip */
    uint32_t af[2][2][4];                     /* [mi][split][4] */
#pragma unroll
    for (int mi = 0; mi < 2; mi++)
#pragma unroll
        for (int s = 0; s < 2; s++) {
            int row = wy * 32 + mi * 16 + (lane & 15);
            int kh  = (lane >> 4) * 8;
            ldsm4(af[mi][s], s2u(&sm.ap.A[s][row][kh]));
        }

    float part = 0.f;

    for (int jt = 0; jt < JCHUNK; jt++) {
        JPack& jb = sm.jb[jt & 1];

        /* prefetch next j-tile into the other buffer (overlaps compute) */
        if (jt + 1 < JCHUNK) {
            const float4* gj = (const float4*)&g_jp[b][jbase + jt + 1];
            float4* sj = (float4*)&sm.jb[(jt + 1) & 1];
            cpa16(s2u(sj + tid), gj + tid);
            cpa16(s2u(sj + tid + 512), gj + tid + 512);
            CPA_COMMIT();
        }

        /* ---- gramian: bf16 3-term split, 24 HMMA/warp ---- */
        uint32_t bfr[2][2][4];                /* [np][split][4] */
#pragma unroll
        for (int np = 0; np < 2; np++)
#pragma unroll
            for (int s = 0; s < 2; s++) {
                int row = wx * 32 + np * 16 + ((lane >> 4) & 1) * 8 + (lane & 7);
                int kh  = ((lane >> 3) & 1) * 8;
                ldsm4(bfr[np][s], s2u(&jb.B[s][row][kh]));
            }

        float acc[2][4][4];
#pragma unroll
        for (int mi = 0; mi < 2; mi++)
#pragma unroll
            for (int ni = 0; ni < 4; ni++) {
#pragma unroll
                for (int k = 0; k < 4; k++) acc[mi][ni][k] = 0.f;
                const int np = ni >> 1, o = (ni & 1) * 2;
                mma_bf16(acc[mi][ni], af[mi][0], bfr[np][0][o], bfr[np][0][o + 1]);
                mma_bf16(acc[mi][ni], af[mi][0], bfr[np][1][o], bfr[np][1][o + 1]);
                mma_bf16(acc[mi][ni], af[mi][1], bfr[np][0][o], bfr[np][0][o + 1]);
            }

        /* ---- RBF weights + combine ---- */
        const int r = lane >> 2;
        ulonglong2 I1[4], I2[4];
#pragma unroll
        for (int q = 0; q < 4; q++) {
            int irow = wy * 32 + q * 8 + r;
            I1[q] = *(const ulonglong2*)&sm.ap.X1i[irow][0];
            I2[q] = *(const ulonglong2*)&sm.ap.X1i[irow][4];
        }

#pragma unroll
        for (int ni = 0; ni < 4; ni++) {
            const int jc = wx * 32 + ni * 8 + 2 * (lane & 3);
            u64 T0 = *(const u64*)&jb.JT[0][jc];
            u64 T1 = *(const u64*)&jb.JT[1][jc];
            u64 T2 = *(const u64*)&jb.JT[2][jc];
            u64 N0 = *(const u64*)&jb.JN[0][jc];
            u64 N1 = *(const u64*)&jb.JN[1][jc];
            u64 N2 = *(const u64*)&jb.JN[2][jc];
            u64 BT = *(const u64*)&jb.bt[jc];
            u64 BN = *(const u64*)&jb.bn[jc];
#pragma unroll
            for (int q = 0; q < 4; q++) {
                const int mi = q >> 1, half = q & 1;
                u64 st = add2(I2[q].y, BT);
                fma2(st, I1[q].x, T0); fma2(st, I1[q].y, T1); fma2(st, I2[q].x, T2);
                u64 sn = add2(I2[q].y, BN);
                fma2(sn, I1[q].x, N0); fma2(sn, I1[q].y, N1); fma2(sn, I2[q].x, N2);
                float2 s = unpk(st), n = unpk(sn);
                float w0 = fexp2(s.x) - fexp2(n.x);
                float w1 = fexp2(s.y) - fexp2(n.y);
                part = fmaf(w0, acc[mi][ni][half * 2],     part);
                part = fmaf(w1, acc[mi][ni][half * 2 + 1], part);
            }
        }

        /* ensure prefetch landed; release current buffer for next prefetch */
        CPA_WAIT0();
        __syncthreads();
    }

    /* ---- block reduce -> one double atomic ---- */
#pragma unroll
    for (int o = 16; o; o >>= 1) part += __shfl_down_sync(0xffffffffu, part, o);
    if (lane == 0) sm.warpsum[w] = part;
    __syncthreads();
    if (tid == 0) {
        float s = 0.f;
#pragma unroll
        for (int k = 0; k < 16; k++) s += sm.warpsum[k];
        atomicAdd(&g_S[b], (double)s);
    }
}

/* ------------------------- finalize ------------------------------------- */
__global__ void fin_kernel(float* out) {
    double tot = 0.0;
    float fns = 0.f;
#pragma unroll
    for (int b = 0; b < BB; b++) {
        float s1 = 0.f, s2 = 0.f;
        for (int k = 0; k < PREPB; k++) {
            fns += g_part[b][k][0];
            s1  += g_part[b][k][1];
            s2  += g_part[b][k][2];
        }
        tot += g_S[b] / ((double)s1 * (double)s2);
    }
    float fl = (float)(-tot);
    out[0] = fl;
    out[1] = fl;
    out[2] = fns * 100.f;
}

/* ------------------------- launch ---------------------------------------- */
extern "C" void kernel_launch(void* const* d_in, const int* in_sizes, int n_in,
                              void* d_out, int out_size) {
    const float* f1   = (const float*)d_in[0];
    const float* f2   = (const float*)d_in[1];
    const float* dp1  = (const float*)d_in[2];
    const float* dp2  = (const float*)d_in[3];
    const float* pose = (const float*)d_in[4];
    const float* yz1  = (const float*)d_in[7];
    float* out = (float*)d_out;

    prep_kernel<<<dim3(PREPB, BB), 256>>>(f1, f2, dp1, dp2, pose, yz1);
    pair_kernel<<<dim3(NJB, NT, BB), 512>>>();
    fin_kernel<<<1, 1>>>(out);
}

// round 14
// speedup vs baseline: 14.2196x; 1.2238x over previous
#include <cuda_runtime.h>
#include <cuda_bf16.h>
#include <cstdint>

#define NPTS 6912
#define CF 16
#define BB 2
#define TILE 128
#define NT (NPTS / TILE)     /* 54 */
#define JCHUNK 6
#define NJB (NT / JCHUNK)    /* 9 */
#define PREPB (NPTS / 256)   /* 27 */
#define EPSF 1e-8f
#define NEG_SCALE (-14.426950408889634f)
#define POS2SCALE (28.853900817779268f)
#define ROWP 24              /* bf16/row: 16 used + 8 pad -> 48B stride */

typedef unsigned long long u64;

/* ------------------------- packed per-tile records ----------------------- */
struct APack {               /* 16384 B */
    __nv_bfloat16 A[2][TILE][ROWP];     /* hi/lo split, 12KB */
    float X1i[TILE][8];                 /* {Px,Px,Py,Py,Pz,Pz,as,as} 4KB */
};
struct JPack {               /* 16384 B */
    __nv_bfloat16 B[2][TILE][ROWP];     /* 12KB */
    float JT[3][TILE];
    float JN[3][TILE];
    float bt[TILE], bn[TILE];
};

__device__ APack g_ap[BB][NT];
__device__ JPack g_jp[BB][NT];
__device__ float  g_part[BB][PREPB][3];
__device__ double g_S[BB];

/* ------------------------- helpers -------------------------------------- */
__device__ __forceinline__ float2 unpk(u64 v) {
    float2 r; asm("mov.b64 {%0, %1}, %2;" : "=f"(r.x), "=f"(r.y) : "l"(v)); return r;
}
__device__ __forceinline__ void fma2(u64 &d, u64 a, u64 b) {
    asm("fma.rn.f32x2 %0, %1, %2, %0;" : "+l"(d) : "l"(a), "l"(b));
}
__device__ __forceinline__ u64 add2(u64 a, u64 b) {
    u64 r; asm("add.rn.f32x2 %0, %1, %2;" : "=l"(r) : "l"(a), "l"(b)); return r;
}
__device__ __forceinline__ float fexp2(float x) {
    float r; asm("ex2.approx.f32 %0, %1;" : "=f"(r) : "f"(x)); return r;
}
__device__ __forceinline__ uint32_t s2u(const void* p) {
    uint32_t a;
    asm("{ .reg .u64 t; cvta.to.shared.u64 t, %1; cvt.u32.u64 %0, t; }" : "=r"(a) : "l"(p));
    return a;
}
__device__ __forceinline__ void ldsm4(uint32_t r[4], uint32_t addr) {
    asm volatile("ldmatrix.sync.aligned.m8n8.x4.shared.b16 {%0,%1,%2,%3}, [%4];"
                 : "=r"(r[0]), "=r"(r[1]), "=r"(r[2]), "=r"(r[3]) : "r"(addr));
}
__device__ __forceinline__ void mma_bf16(float d[4], const uint32_t a[4],
                                         uint32_t b0, uint32_t b1) {
    asm volatile("mma.sync.aligned.m16n8k16.row.col.f32.bf16.bf16.f32 "
                 "{%0,%1,%2,%3}, {%4,%5,%6,%7}, {%8,%9}, {%0,%1,%2,%3};"
                 : "+f"(d[0]), "+f"(d[1]), "+f"(d[2]), "+f"(d[3])
                 : "r"(a[0]), "r"(a[1]), "r"(a[2]), "r"(a[3]), "r"(b0), "r"(b1));
}
__device__ __forceinline__ void cpa16(uint32_t dst, const void* src) {
    asm volatile("cp.async.cg.shared.global [%0], [%1], 16;" :: "r"(dst), "l"(src));
}
#define CPA_COMMIT() asm volatile("cp.async.commit_group;" ::: "memory")
#define CPA_WAIT0()  asm volatile("cp.async.wait_group 0;" ::: "memory")

/* ------------------------- prep ----------------------------------------- */
__global__ void prep_kernel(const float* __restrict__ f1, const float* __restrict__ f2,
                            const float* __restrict__ dp1, const float* __restrict__ dp2,
                            const float* __restrict__ pose, const float* __restrict__ yz1) {
    const int b = blockIdx.y;
    const int i = blockIdx.x * blockDim.x + threadIdx.x;
    const int tile = i >> 7, row = i & 127;
    float fns, m1c, m2c;
    {
        float d1 = dp1[b * NPTS + i], d2 = dp2[b * NPTS + i];
        float m1 = (d1 > 0.f) ? 1.f : 0.f;
        float m2 = (d2 > 0.f) ? 1.f : 0.f;
        float v1[CF], v2[CF];
        float s1 = 0.f, s2 = 0.f;
#pragma unroll
        for (int c = 0; c < CF; c++) {
            v1[c] = f1[((size_t)b * CF + c) * NPTS + i];
            v2[c] = f2[((size_t)b * CF + c) * NPTS + i];
            s1 = fmaf(v1[c], v1[c], s1);
            s2 = fmaf(v2[c], v2[c], s2);
        }
        float n1 = sqrtf(s1), n2 = sqrtf(s2);
        float iv1 = m1 / (n1 + EPSF), iv2 = m2 / (n2 + EPSF);

        union { uint4 q[2]; __nv_bfloat162 h[8]; } AH, AL, BH, BL;
#pragma unroll
        for (int t = 0; t < 8; t++) {
            float a0 = v1[2 * t] * iv1,     a1 = v1[2 * t + 1] * iv1;
            __nv_bfloat16 h0 = __float2bfloat16(a0), h1 = __float2bfloat16(a1);
            AH.h[t].x = h0; AH.h[t].y = h1;
            AL.h[t].x = __float2bfloat16(a0 - __bfloat162float(h0));
            AL.h[t].y = __float2bfloat16(a1 - __bfloat162float(h1));
            float b0 = v2[2 * t] * iv2,     b1 = v2[2 * t + 1] * iv2;
            __nv_bfloat16 g0 = __float2bfloat16(b0), g1 = __float2bfloat16(b1);
            BH.h[t].x = g0; BH.h[t].y = g1;
            BL.h[t].x = __float2bfloat16(b0 - __bfloat162float(g0));
            BL.h[t].y = __float2bfloat16(b1 - __bfloat162float(g1));
        }
        APack& ap = g_ap[b][tile];
        JPack& jp = g_jp[b][tile];
        *(uint4*)&ap.A[0][row][0] = AH.q[0];
        *(uint4*)&ap.A[0][row][8] = AH.q[1];
        *(uint4*)&ap.A[1][row][0] = AL.q[0];
        *(uint4*)&ap.A[1][row][8] = AL.q[1];
        *(uint4*)&jp.B[0][row][0] = BH.q[0];
        *(uint4*)&jp.B[0][row][8] = BH.q[1];
        *(uint4*)&jp.B[1][row][0] = BL.q[0];
        *(uint4*)&jp.B[1][row][8] = BL.q[1];

        float y0 = yz1[i], y1 = yz1[NPTS + i], y2 = yz1[2 * NPTS + i];
        float ax = y0 * d1, ay = y1 * d1, az = y2 * d1;
        float as = NEG_SCALE * (ax * ax + ay * ay + az * az);
        *(float4*)&ap.X1i[row][0] = make_float4(POS2SCALE * ax, POS2SCALE * ax,
                                                POS2SCALE * ay, POS2SCALE * ay);
        *(float4*)&ap.X1i[row][4] = make_float4(POS2SCALE * az, POS2SCALE * az, as, as);

        float bx = y0 * d2, by = y1 * d2, bz = y2 * d2;
        jp.JN[0][row] = bx; jp.JN[1][row] = by; jp.JN[2][row] = bz;
        jp.bn[row] = NEG_SCALE * (bx * bx + by * by + bz * bz);
        const float* P = pose + b * 16;
        float tx = P[0] * bx + P[1] * by + P[2]  * bz + P[3];
        float ty = P[4] * bx + P[5] * by + P[6]  * bz + P[7];
        float tz = P[8] * bx + P[9] * by + P[10] * bz + P[11];
        jp.JT[0][row] = tx; jp.JT[1][row] = ty; jp.JT[2][row] = tz;
        jp.bt[row] = NEG_SCALE * (tx * tx + ty * ty + tz * tz);
        fns = n1 * m1 + n2 * m2; m1c = m1; m2c = m2;
    }
#pragma unroll
    for (int o = 16; o; o >>= 1) {
        fns += __shfl_down_sync(0xffffffffu, fns, o);
        m1c += __shfl_down_sync(0xffffffffu, m1c, o);
        m2c += __shfl_down_sync(0xffffffffu, m2c, o);
    }
    __shared__ float rf[8], r1[8], r2[8];
    int w = threadIdx.x >> 5, l = threadIdx.x & 31;
    if (l == 0) { rf[w] = fns; r1[w] = m1c; r2[w] = m2c; }
    __syncthreads();
    if (threadIdx.x == 0) {
        float a = 0.f, c1 = 0.f, c2 = 0.f;
#pragma unroll
        for (int k = 0; k < 8; k++) { a += rf[k]; c1 += r1[k]; c2 += r2[k]; }
        g_part[b][blockIdx.x][0] = a;
        g_part[b][blockIdx.x][1] = c1;
        g_part[b][blockIdx.x][2] = c2;
        if (blockIdx.x == 0) g_S[b] = 0.0;
    }
}

/* --------- pair: 64-row half-strip, 256 threads, 2 blocks/SM ------------ */
struct SmemT {
    __nv_bfloat16 A[2][64][ROWP];       /* 6KB (contig 384 float4) */
    float X1i[64][8];                   /* 2KB (contig 128 float4) */
    JPack jb[2];                        /* 32KB double buffer */
    float warpsum[8];
};

__global__ void __launch_bounds__(256, 2) pair_kernel() {
    __shared__ SmemT sm;
    const int b     = blockIdx.z;
    const int ti    = blockIdx.y >> 1;
    const int ihalf = blockIdx.y & 1;
    const int jbase = blockIdx.x * JCHUNK;
    const int tid = threadIdx.x;
    const int w = tid >> 5, lane = tid & 31;
    const int wy = w >> 2, wx = w & 3;       /* 2x4 warps of 32x32 slabs */

    /* prologue: async-fill A-half (3 contig chunks) + first J-pack */
    {
        const char* gA = (const char*)&g_ap[b][ti];
        float4* sa = (float4*)&sm;           /* A then X1i, contiguous 512 f4 */
#pragma unroll
        for (int k = 0; k < 2; k++) {
            int idx = tid + k * 256;
            const char* src;
            if (idx < 192)      src = gA + (size_t)ihalf * 3072 + (size_t)idx * 16;
            else if (idx < 384) src = gA + 6144 + (size_t)ihalf * 3072 + (size_t)(idx - 192) * 16;
            else                src = gA + 12288 + (size_t)ihalf * 2048 + (size_t)(idx - 384) * 16;
            cpa16(s2u(sa + idx), src);
        }
        const float4* gj = (const float4*)&g_jp[b][jbase];
        float4* sj = (float4*)&sm.jb[0];
#pragma unroll
        for (int k = 0; k < 4; k++)
            cpa16(s2u(sj + tid + k * 256), gj + tid + k * 256);
        CPA_COMMIT();
        CPA_WAIT0();
    }
    __syncthreads();

    /* A fragments + i-geometry: pinned in registers for the whole strip */
    uint32_t af[2][2][4];                     /* [mi][split][4] */
#pragma unroll
    for (int mi = 0; mi < 2; mi++)
#pragma unroll
        for (int s = 0; s < 2; s++) {
            int row = wy * 32 + mi * 16 + (lane & 15);
            int kh  = (lane >> 4) * 8;
            ldsm4(af[mi][s], s2u(&sm.A[s][row][kh]));
        }
    const int r = lane >> 2;
    ulonglong2 I1[4], I2[4];                  /* q = mi*2+half */
#pragma unroll
    for (int q = 0; q < 4; q++) {
        int irow = wy * 32 + q * 8 + r;
        I1[q] = *(const ulonglong2*)&sm.X1i[irow][0];
        I2[q] = *(const ulonglong2*)&sm.X1i[irow][4];
    }

    float part = 0.f;

    for (int jt = 0; jt < JCHUNK; jt++) {
        JPack& jb = sm.jb[jt & 1];

        /* prefetch next j-tile into the other buffer (overlaps compute) */
        if (jt + 1 < JCHUNK) {
            const float4* gj = (const float4*)&g_jp[b][jbase + jt + 1];
            float4* sj = (float4*)&sm.jb[(jt + 1) & 1];
#pragma unroll
            for (int k = 0; k < 4; k++)
                cpa16(s2u(sj + tid + k * 256), gj + tid + k * 256);
            CPA_COMMIT();
        }

        /* ---- gramian: bf16 3-term split, 24 HMMA/warp ---- */
        uint32_t bfr[2][2][4];                /* [np][split][4] */
#pragma unroll
        for (int np = 0; np < 2; np++)
#pragma unroll
            for (int s = 0; s < 2; s++) {
                int row = wx * 32 + np * 16 + ((lane >> 4) & 1) * 8 + (lane & 7);
                int kh  = ((lane >> 3) & 1) * 8;
                ldsm4(bfr[np][s], s2u(&jb.B[s][row][kh]));
            }

        float acc[2][4][4];
#pragma unroll
        for (int mi = 0; mi < 2; mi++)
#pragma unroll
            for (int ni = 0; ni < 4; ni++) {
#pragma unroll
                for (int k = 0; k < 4; k++) acc[mi][ni][k] = 0.f;
                const int np = ni >> 1, o = (ni & 1) * 2;
                mma_bf16(acc[mi][ni], af[mi][0], bfr[np][0][o], bfr[np][0][o + 1]);
                mma_bf16(acc[mi][ni], af[mi][0], bfr[np][1][o], bfr[np][1][o + 1]);
                mma_bf16(acc[mi][ni], af[mi][1], bfr[np][0][o], bfr[np][0][o + 1]);
            }

        /* ---- RBF weights + combine ---- */
#pragma unroll
        for (int ni = 0; ni < 4; ni++) {
            const int jc = wx * 32 + ni * 8 + 2 * (lane & 3);
            u64 T0 = *(const u64*)&jb.JT[0][jc];
            u64 T1 = *(const u64*)&jb.JT[1][jc];
            u64 T2 = *(const u64*)&jb.JT[2][jc];
            u64 N0 = *(const u64*)&jb.JN[0][jc];
            u64 N1 = *(const u64*)&jb.JN[1][jc];
            u64 N2 = *(const u64*)&jb.JN[2][jc];
            u64 BT = *(const u64*)&jb.bt[jc];
            u64 BN = *(const u64*)&jb.bn[jc];
#pragma unroll
            for (int q = 0; q < 4; q++) {
                const int mi = q >> 1, half = q & 1;
                u64 st = add2(I2[q].y, BT);
                fma2(st, I1[q].x, T0); fma2(st, I1[q].y, T1); fma2(st, I2[q].x, T2);
                u64 sn = add2(I2[q].y, BN);
                fma2(sn, I1[q].x, N0); fma2(sn, I1[q].y, N1); fma2(sn, I2[q].x, N2);
                float2 s = unpk(st), n = unpk(sn);
                float w0 = fexp2(s.x) - fexp2(n.x);
                float w1 = fexp2(s.y) - fexp2(n.y);
                part = fmaf(w0, acc[mi][ni][half * 2],     part);
                part = fmaf(w1, acc[mi][ni][half * 2 + 1], part);
            }
        }

        /* ensure prefetch landed; release current buffer for next prefetch */
        CPA_WAIT0();
        __syncthreads();
    }

    /* ---- block reduce -> one double atomic ---- */
#pragma unroll
    for (int o = 16; o; o >>= 1) part += __shfl_down_sync(0xffffffffu, part, o);
    if (lane == 0) sm.warpsum[w] = part;
    __syncthreads();
    if (tid == 0) {
        float s = 0.f;
#pragma unroll
        for (int k = 0; k < 8; k++) s += sm.warpsum[k];
        atomicAdd(&g_S[b], (double)s);
    }
}

/* ------------------------- finalize ------------------------------------- */
__global__ void fin_kernel(float* out) {
    double tot = 0.0;
    float fns = 0.f;
#pragma unroll
    for (int b = 0; b < BB; b++) {
        float s1 = 0.f, s2 = 0.f;
        for (int k = 0; k < PREPB; k++) {
            fns += g_part[b][k][0];
            s1  += g_part[b][k][1];
            s2  += g_part[b][k][2];
        }
        tot += g_S[b] / ((double)s1 * (double)s2);
    }
    float fl = (float)(-tot);
    out[0] = fl;
    out[1] = fl;
    out[2] = fns * 100.f;
}

/* ------------------------- launch ---------------------------------------- */
extern "C" void kernel_launch(void* const* d_in, const int* in_sizes, int n_in,
                              void* d_out, int out_size) {
    const float* f1   = (const float*)d_in[0];
    const float* f2   = (const float*)d_in[1];
    const float* dp1  = (const float*)d_in[2];
    const float* dp2  = (const float*)d_in[3];
    const float* pose = (const float*)d_in[4];
    const float* yz1  = (const float*)d_in[7];
    float* out = (float*)d_out;

    prep_kernel<<<dim3(PREPB, BB), 256>>>(f1, f2, dp1, dp2, pose, yz1);
    pair_kernel<<<dim3(NJB, NT * 2, BB), 256>>>();
    fin_kernel<<<1, 1>>>(out);
}